// round 13
// baseline (speedup 1.0000x reference)
#include <cuda_runtime.h>
#include <math.h>

#define NTOK 8192
#define DM   1024
#define PROJ 256
#define RHID 256
#define EHID 256
#define NE   8
#define RAWF 512
#define RIN  1280

// output layout (floats), tuple order flattened
#define OFF_NEXT   0L
#define OFF_STAGE  8388608L
#define OFF_GATE   16777216L
#define OFF_SCALED 16842752L
#define OFF_GROUP  16908288L
#define OFF_RULE   16941056L

// scratch (device globals; no allocation allowed)
static __device__ __align__(16) float g_hnorm[NTOK * DM];
static __device__ __align__(16) float g_rin[NTOK * RIN];
static __device__ __align__(16) float g_rh1[NTOK * RHID];
static __device__ __align__(16) float g_logits[NTOK * NE];
static __device__ __align__(16) float g_Hbuf[(long)NE * NTOK * EHID];
static __device__ __align__(16) float g_rw1f[RIN * RHID];   // fused router W1
static __device__ __align__(16) float g_rb1f[RHID];         // fused router b1
static __device__ int g_cnt[NE];
static __device__ int g_idx[NE * NTOK];

__device__ __forceinline__ float gelu_f(float x) {
    const float c = 0.7978845608028654f;
    float t = tanhf(c * (x + 0.044715f * x * x * x));
    return 0.5f * x * (1.0f + t);
}

__device__ __forceinline__ float warpsum(float v) {
    #pragma unroll
    for (int o = 16; o; o >>= 1) v += __shfl_xor_sync(0xFFFFFFFFu, v, o);
    return v;
}

__device__ __forceinline__ float cvt_tf32(float x) {
    unsigned u;
    asm("cvt.rna.tf32.f32 %0, %1;" : "=r"(u) : "f"(x));
    return __uint_as_float(u);
}

__device__ __forceinline__ void mma8(float* c, const unsigned* a, const unsigned* b) {
    asm volatile(
        "mma.sync.aligned.m16n8k8.row.col.f32.tf32.tf32.f32 "
        "{%0,%1,%2,%3}, {%4,%5,%6,%7}, {%8,%9}, {%0,%1,%2,%3};"
        : "+f"(c[0]), "+f"(c[1]), "+f"(c[2]), "+f"(c[3])
        : "r"(a[0]), "r"(a[1]), "r"(a[2]), "r"(a[3]),
          "r"(b[0]), "r"(b[1]));
}

// ---------------------------------------------------------------------------
// Weight fusion: g_rw1f[0:1024] = r_w1[0:1024];
//                g_rw1f[1024+k] = fp_w2[k] @ r_w1[1024:]  (k = 0..255)
//                g_rb1f = r_b1 + fp_b2 @ r_w1[1024:]
// Exact fp32; eliminates the fp-proj layer-2 GEMM entirely.
// ---------------------------------------------------------------------------
__global__ void __launch_bounds__(256) fuse_kernel(
    const float* __restrict__ fp_w2, const float* __restrict__ fp_b2,
    const float* __restrict__ r_w1,  const float* __restrict__ r_b1)
{
    int b = blockIdx.x;
    int n = threadIdx.x;
    if (b < DM) {
        g_rw1f[b * RHID + n] = r_w1[b * RHID + n];
    } else if (b < RIN) {
        int k = b - DM;
        float a0 = 0.f, a1 = 0.f, a2 = 0.f, a3 = 0.f;
        #pragma unroll 4
        for (int j = 0; j < PROJ; j += 4) {
            a0 += fp_w2[k * PROJ + j + 0] * r_w1[(DM + j + 0) * RHID + n];
            a1 += fp_w2[k * PROJ + j + 1] * r_w1[(DM + j + 1) * RHID + n];
            a2 += fp_w2[k * PROJ + j + 2] * r_w1[(DM + j + 2) * RHID + n];
            a3 += fp_w2[k * PROJ + j + 3] * r_w1[(DM + j + 3) * RHID + n];
        }
        g_rw1f[b * RHID + n] = (a0 + a1) + (a2 + a3);
    } else {
        float acc = r_b1[n];
        for (int j = 0; j < PROJ; j++)
            acc += fp_b2[j] * r_w1[(DM + j) * RHID + n];
        g_rb1f[n] = acc;
    }
}

// ---------------------------------------------------------------------------
// Kernel 1: layernorm -> g_hnorm and g_rin[:, :1024]; rule logits; zero
// stage_out region of d_out; zero g_cnt (block 0).
// ---------------------------------------------------------------------------
__global__ void __launch_bounds__(256) ln_kernel(
    const float* __restrict__ hidden,
    const float* __restrict__ ln_g, const float* __restrict__ ln_b,
    const float* __restrict__ feat,
    const float* __restrict__ rr_w, const float* __restrict__ rr_b,
    float* __restrict__ out)
{
    int t = blockIdx.x;
    int tid = threadIdx.x;
    long base = (long)t * DM + tid * 4;
    float4 x = *(const float4*)(hidden + base);

    float s1 = x.x + x.y + x.z + x.w;
    float s2 = x.x * x.x + x.y * x.y + x.z * x.z + x.w * x.w;

    __shared__ float sm1[8], sm2[8];
    float w1 = warpsum(s1), w2 = warpsum(s2);
    if ((tid & 31) == 0) { sm1[tid >> 5] = w1; sm2[tid >> 5] = w2; }
    __syncthreads();
    __shared__ float s_mu, s_inv;
    if (tid == 0) {
        float a = 0.f, c = 0.f;
        #pragma unroll
        for (int i = 0; i < 8; i++) { a += sm1[i]; c += sm2[i]; }
        float m = a * (1.0f / DM);
        float var = c * (1.0f / DM) - m * m;
        s_mu = m;
        s_inv = rsqrtf(var + 1e-5f);
    }
    __syncthreads();
    float mu = s_mu, inv = s_inv;

    float4 gg = *(const float4*)(ln_g + tid * 4);
    float4 bb = *(const float4*)(ln_b + tid * 4);
    float4 y;
    y.x = (x.x - mu) * inv * gg.x + bb.x;
    y.y = (x.y - mu) * inv * gg.y + bb.y;
    y.z = (x.z - mu) * inv * gg.z + bb.z;
    y.w = (x.w - mu) * inv * gg.w + bb.w;

    *(float4*)(g_hnorm + base) = y;
    *(float4*)(g_rin + (long)t * RIN + tid * 4) = y;

    float4 z4 = make_float4(0.f, 0.f, 0.f, 0.f);
    *(float4*)(out + OFF_STAGE + base) = z4;

    if (tid < NE) {
        float acc = rr_b[tid];
        #pragma unroll
        for (int k = 0; k < 16; k++) acc += feat[t * 16 + k] * rr_w[k * NE + tid];
        out[OFF_RULE + (long)t * NE + tid] = acc;
    }
    if (t == 0 && tid < NE) g_cnt[tid] = 0;
}

// ---------------------------------------------------------------------------
// tf32 tensor-core GEMM, templated precision:
//   PREC=3: 3xtf32 split (fp32-grade, routing-critical GEMMs)
//   PREC=1: single-pass tf32 (~2e-4, expert GEMMs after gating)
// Double-buffered SMEM, one __syncthreads per K-slab.
// CTA tile 128x128x16, 256 threads = 8 warps (2x4), warp tile 64x32.
//
// SMEM layouts are PERMUTED so fragment loads vectorize (same values, new
// addresses — numerics identical to the scalar-LDS version):
//   A [m][k'] with k' = (k&8) | 2*(k&3) | ((k>>2)&1):
//     thread (g,q) frag pair (k=q, k=q+4) adjacent -> LDS.64 per row.
//   B [k][n'] with n' = 16*(n&7) + (n>>3), BPAD=132 (=4 mod 32):
//     the four bh[nt][.] lanes (n = wn+8nt+g) contiguous -> LDS.128.
// mode: 0 = store, 1 = gelu+store, 2 = weighted atomic scatter to stage_out.
// gatherA: A rows indirected through idx (expert GEMM1).
// ---------------------------------------------------------------------------
#define TBM 128
#define TBN 128
#define TBK 16
#define APAD 20
#define BPAD 132

template<int PREC>
__global__ void __launch_bounds__(256) mma_gemm(
    const float* __restrict__ A,
    const float* __restrict__ Bw,
    const float* __restrict__ bias,
    float* __restrict__ C,
    int N, int K, int lda, int ldc,
    long aStride, long bStride, long cStride, int biasStride,
    const int* __restrict__ gIdx,
    const int* __restrict__ cntArr,
    int Mfixed, int mode, int gatherA,
    float* __restrict__ outbase)
{
    int z = blockIdx.z;
    int M = cntArr ? cntArr[z] : Mfixed;
    int m0 = blockIdx.y * TBM;
    if (m0 >= M) return;
    int n0 = blockIdx.x * TBN;
    const float* Az = A + (long)z * aStride;
    const float* B = Bw + (long)z * bStride;
    float* Cz = C + (long)z * cStride;
    const float* bz = bias + (long)z * biasStride;
    const int* idx = gIdx ? (gIdx + z * NTOK) : (const int*)0;

    __shared__ __align__(16) float As_hi[2][TBM][APAD];
    __shared__ __align__(16) float Bs_hi[2][TBK][BPAD];
    __shared__ __align__(16) float As_lo[PREC == 3 ? 2 : 1][TBM][APAD];
    __shared__ __align__(16) float Bs_lo[PREC == 3 ? 2 : 1][TBK][BPAD];

    int tid = threadIdx.x;

    // A staging: 2 float4/thread; id -> m-row = id>>2, k-quad = id&3
    long aOff[2]; bool aV[2];
    #pragma unroll
    for (int j = 0; j < 2; j++) {
        int id = tid + 256 * j;
        int r = id >> 2, c4 = id & 3;
        int gm = m0 + r;
        aV[j] = gm < M;
        int gr = 0;
        if (aV[j]) gr = gatherA ? idx[gm] : gm;
        aOff[j] = (long)gr * lda + c4 * 4;
    }

    float4 ra[2], rb[2];
    #pragma unroll
    for (int j = 0; j < 2; j++)
        ra[j] = aV[j] ? *(const float4*)(Az + aOff[j]) : make_float4(0.f,0.f,0.f,0.f);
    #pragma unroll
    for (int j = 0; j < 2; j++) {
        int id = tid + 256 * j;
        int r = id >> 5, c4 = id & 31;
        rb[j] = *(const float4*)(B + (long)r * N + n0 + c4 * 4);
    }

    float acc[4][4][4];
    #pragma unroll
    for (int a = 0; a < 4; a++)
        #pragma unroll
        for (int b = 0; b < 4; b++)
            #pragma unroll
            for (int cc = 0; cc < 4; cc++) acc[a][b][cc] = 0.f;

    int wid = tid >> 5, lane = tid & 31;
    int wm = (wid >> 2) * 64, wn = (wid & 3) * 32;
    int g = lane >> 2, q = lane & 3;
    int colB = 16 * g + (wn >> 3);   // permuted B fragment column

    int buf = 0;
    for (int k0 = 0; k0 < K; k0 += TBK) {
        // commit staged regs to smem[buf] (permuted layouts)
        #pragma unroll
        for (int j = 0; j < 2; j++) {
            int id = tid + 256 * j;
            int r = id >> 2, c4 = id & 3;
            // k = 4*c4 + i  ->  k' = 8*(c4>>1) + (c4&1) + 2*i
            int cb = 8 * (c4 >> 1) + (c4 & 1);
            float v[4] = { ra[j].x, ra[j].y, ra[j].z, ra[j].w };
            #pragma unroll
            for (int i = 0; i < 4; i++) {
                float h = cvt_tf32(v[i]);
                As_hi[buf][r][cb + 2 * i] = h;
                if (PREC == 3) As_lo[buf][r][cb + 2 * i] = cvt_tf32(v[i] - h);
            }
        }
        #pragma unroll
        for (int j = 0; j < 2; j++) {
            int id = tid + 256 * j;
            int r = id >> 5, n4 = id & 31;
            // n = 4*n4 + i  ->  n' = 64*(n4&1) + 16*i + (n4>>1)
            int cb = 64 * (n4 & 1) + (n4 >> 1);
            float v[4] = { rb[j].x, rb[j].y, rb[j].z, rb[j].w };
            #pragma unroll
            for (int i = 0; i < 4; i++) {
                float h = cvt_tf32(v[i]);
                Bs_hi[buf][r][cb + 16 * i] = h;
                if (PREC == 3) Bs_lo[buf][r][cb + 16 * i] = cvt_tf32(v[i] - h);
            }
        }
        __syncthreads();

        // prefetch next K-slab into regs (overlaps with compute below)
        if (k0 + TBK < K) {
            #pragma unroll
            for (int j = 0; j < 2; j++)
                ra[j] = aV[j] ? *(const float4*)(Az + aOff[j] + k0 + TBK)
                              : make_float4(0.f,0.f,0.f,0.f);
            #pragma unroll
            for (int j = 0; j < 2; j++) {
                int id = tid + 256 * j;
                int r = id >> 5, c4 = id & 31;
                rb[j] = *(const float4*)(B + (long)(k0 + TBK + r) * N + n0 + c4 * 4);
            }
        }

        #pragma unroll
        for (int ks = 0; ks < 2; ks++) {
            int kk = ks * 8;
            int ca = kk + 2 * q;              // permuted A fragment column
            unsigned ah[4][4], al[4][4], bh[4][2], bl[4][2];
            #pragma unroll
            for (int mt = 0; mt < 4; mt++) {
                int mr = wm + mt * 16 + g;
                float2 p0 = *(const float2*)&As_hi[buf][mr][ca];
                float2 p1 = *(const float2*)&As_hi[buf][mr + 8][ca];
                ah[mt][0] = __float_as_uint(p0.x);
                ah[mt][2] = __float_as_uint(p0.y);
                ah[mt][1] = __float_as_uint(p1.x);
                ah[mt][3] = __float_as_uint(p1.y);
                if (PREC == 3) {
                    float2 l0 = *(const float2*)&As_lo[buf][mr][ca];
                    float2 l1 = *(const float2*)&As_lo[buf][mr + 8][ca];
                    al[mt][0] = __float_as_uint(l0.x);
                    al[mt][2] = __float_as_uint(l0.y);
                    al[mt][1] = __float_as_uint(l1.x);
                    al[mt][3] = __float_as_uint(l1.y);
                }
            }
            {
                float4 b0 = *(const float4*)&Bs_hi[buf][kk + q][colB];
                float4 b1 = *(const float4*)&Bs_hi[buf][kk + q + 4][colB];
                bh[0][0] = __float_as_uint(b0.x); bh[1][0] = __float_as_uint(b0.y);
                bh[2][0] = __float_as_uint(b0.z); bh[3][0] = __float_as_uint(b0.w);
                bh[0][1] = __float_as_uint(b1.x); bh[1][1] = __float_as_uint(b1.y);
                bh[2][1] = __float_as_uint(b1.z); bh[3][1] = __float_as_uint(b1.w);
                if (PREC == 3) {
                    float4 c0 = *(const float4*)&Bs_lo[buf][kk + q][colB];
                    float4 c1 = *(const float4*)&Bs_lo[buf][kk + q + 4][colB];
                    bl[0][0] = __float_as_uint(c0.x); bl[1][0] = __float_as_uint(c0.y);
                    bl[2][0] = __float_as_uint(c0.z); bl[3][0] = __float_as_uint(c0.w);
                    bl[0][1] = __float_as_uint(c1.x); bl[1][1] = __float_as_uint(c1.y);
                    bl[2][1] = __float_as_uint(c1.z); bl[3][1] = __float_as_uint(c1.w);
                }
            }
            #pragma unroll
            for (int mt = 0; mt < 4; mt++)
                #pragma unroll
                for (int nt = 0; nt < 4; nt++) {
                    if (PREC == 3) {
                        mma8(acc[mt][nt], al[mt], bh[nt]);
                        mma8(acc[mt][nt], ah[mt], bl[nt]);
                    }
                    mma8(acc[mt][nt], ah[mt], bh[nt]);
                }
        }
        buf ^= 1;
    }

    // epilogue
    #pragma unroll
    for (int mt = 0; mt < 4; mt++) {
        int r0 = m0 + wm + mt * 16 + g;
        int r1 = r0 + 8;
        #pragma unroll
        for (int nt = 0; nt < 4; nt++) {
            int col = n0 + wn + nt * 8 + 2 * q;
            float b0 = bz[col], b1 = bz[col + 1];
            float v00 = acc[mt][nt][0] + b0, v01 = acc[mt][nt][1] + b1;
            float v10 = acc[mt][nt][2] + b0, v11 = acc[mt][nt][3] + b1;
            if (mode == 1) {
                v00 = gelu_f(v00); v01 = gelu_f(v01);
                v10 = gelu_f(v10); v11 = gelu_f(v11);
            }
            if (mode <= 1) {
                if (r0 < M) { float2 v = make_float2(v00, v01);
                              *(float2*)(Cz + (long)r0 * ldc + col) = v; }
                if (r1 < M) { float2 v = make_float2(v10, v11);
                              *(float2*)(Cz + (long)r1 * ldc + col) = v; }
            } else {
                if (r0 < M) {
                    int tok = idx[r0];
                    float w = outbase[OFF_GATE + (long)tok * NE + z];
                    float* dst = outbase + OFF_STAGE + (long)tok * DM + col;
                    atomicAdd(dst + 0, w * v00);
                    atomicAdd(dst + 1, w * v01);
                }
                if (r1 < M) {
                    int tok = idx[r1];
                    float w = outbase[OFF_GATE + (long)tok * NE + z];
                    float* dst = outbase + OFF_STAGE + (long)tok * DM + col;
                    atomicAdd(dst + 0, w * v10);
                    atomicAdd(dst + 1, w * v11);
                }
            }
        }
    }
}

// ---------------------------------------------------------------------------
// Router logits: g_logits = g_rh1 @ r_w2 + r_b2   (N=8, fp32)
// ---------------------------------------------------------------------------
__global__ void __launch_bounds__(256) logits_kernel(
    const float* __restrict__ r_w2, const float* __restrict__ r_b2)
{
    __shared__ float sh[32 * 257];
    __shared__ float w2s[RHID * NE];
    int tid = threadIdx.x;
    int t0 = blockIdx.x * 32;
    for (int i = tid; i < 32 * RHID; i += 256) {
        int r = i >> 8, c = i & 255;
        sh[r * 257 + c] = g_rh1[(long)(t0 + r) * RHID + c];
    }
    for (int i = tid; i < RHID * NE; i += 256) w2s[i] = r_w2[i];
    __syncthreads();
    int j = tid >> 3, e = tid & 7;
    float acc = r_b2[e];
    #pragma unroll 8
    for (int k = 0; k < RHID; k++) acc += sh[j * 257 + k] * w2s[k * NE + e];
    g_logits[(long)(t0 + j) * NE + e] = acc;
}

// ---------------------------------------------------------------------------
// Gate: exact top-2-with-ties softmax, write gate/scaled/group outputs,
// build per-expert token lists.
// ---------------------------------------------------------------------------
__global__ void __launch_bounds__(256) gate_kernel(float* __restrict__ out)
{
    int t = blockIdx.x * blockDim.x + threadIdx.x;
    if (t >= NTOK) return;
    float l[8];
    #pragma unroll
    for (int e = 0; e < NE; e++) l[e] = g_logits[(long)t * NE + e];

    float m1 = -INFINITY, m2 = -INFINITY;
    #pragma unroll
    for (int e = 0; e < NE; e++) {
        float v = l[e];
        if (v > m1) { m2 = m1; m1 = v; }
        else if (v > m2) { m2 = v; }
    }
    float thresh = m2;

    float w[8];
    float sum = 0.f;
    #pragma unroll
    for (int e = 0; e < NE; e++) {
        if (l[e] >= thresh) { w[e] = expf(l[e] - m1); sum += w[e]; }
        else w[e] = 0.f;
    }
    float rinv = 1.0f / sum;
    #pragma unroll
    for (int e = 0; e < NE; e++) {
        float ww = w[e] * rinv;
        out[OFF_GATE + (long)t * NE + e] = ww;
        out[OFF_SCALED + (long)t * NE + e] = l[e];
        if (l[e] >= thresh) {
            int s = atomicAdd(&g_cnt[e], 1);
            g_idx[e * NTOK + s] = t;
        }
        w[e] = ww;
    }
    #pragma unroll
    for (int g = 0; g < NE / 2; g++)
        out[OFF_GROUP + (long)t * (NE / 2) + g] = w[2 * g] + w[2 * g + 1];
}

// ---------------------------------------------------------------------------
// Final: next_hidden = hidden + alpha * stage_out
// ---------------------------------------------------------------------------
__global__ void __launch_bounds__(256) final_kernel(
    const float* __restrict__ hidden,
    const float* __restrict__ alpha,
    float* __restrict__ out)
{
    long i = ((long)blockIdx.x * 256 + threadIdx.x) * 4;
    float a = *alpha;
    float4 h = *(const float4*)(hidden + i);
    float4 s = *(const float4*)(out + OFF_STAGE + i);
    float4 n;
    n.x = h.x + a * s.x; n.y = h.y + a * s.y;
    n.z = h.z + a * s.z; n.w = h.w + a * s.w;
    *(float4*)(out + OFF_NEXT + i) = n;
}

// ---------------------------------------------------------------------------
extern "C" void kernel_launch(void* const* d_in, const int* in_sizes, int n_in,
                              void* d_out, int out_size)
{
    const float* hidden = (const float*)d_in[0];
    const float* feat   = (const float*)d_in[1];
    const float* bank   = (const float*)d_in[2];   // (tok, 512)
    const float* ln_g  = (const float*)d_in[4];
    const float* ln_b  = (const float*)d_in[5];
    const float* fp_w1 = (const float*)d_in[6];
    const float* fp_b1 = (const float*)d_in[7];
    const float* fp_w2 = (const float*)d_in[8];
    const float* fp_b2 = (const float*)d_in[9];
    const float* r_w1  = (const float*)d_in[10];
    const float* r_b1  = (const float*)d_in[11];
    const float* r_w2  = (const float*)d_in[12];
    const float* r_b2  = (const float*)d_in[13];
    const float* rr_w  = (const float*)d_in[14];
    const float* rr_b  = (const float*)d_in[15];
    const float* e_w1  = (const float*)d_in[16];
    const float* e_b1  = (const float*)d_in[17];
    const float* e_w2  = (const float*)d_in[18];
    const float* e_b2  = (const float*)d_in[19];
    const float* alpha = (const float*)d_in[20];
    float* out = (float*)d_out;

    float *p_hnorm, *p_rin, *p_rh1, *p_Hbuf, *p_rw1f, *p_rb1f;
    int *p_cnt, *p_idx;
    cudaGetSymbolAddress((void**)&p_hnorm, g_hnorm);
    cudaGetSymbolAddress((void**)&p_rin,   g_rin);
    cudaGetSymbolAddress((void**)&p_rh1,   g_rh1);
    cudaGetSymbolAddress((void**)&p_Hbuf,  g_Hbuf);
    cudaGetSymbolAddress((void**)&p_rw1f,  g_rw1f);
    cudaGetSymbolAddress((void**)&p_rb1f,  g_rb1f);
    cudaGetSymbolAddress((void**)&p_cnt,   g_cnt);
    cudaGetSymbolAddress((void**)&p_idx,   g_idx);

    // 0. fuse fp_w2 into router W1 (exact fp32; removes fp-proj GEMM 2)
    fuse_kernel<<<RIN + 1, 256>>>(fp_w2, fp_b2, r_w1, r_b1);

    // 1. layernorm (+ rule logits, zero stage_out & counters)
    ln_kernel<<<NTOK, 256>>>(hidden, ln_g, ln_b, feat, rr_w, rr_b, out);

    // 2. feat proj layer 1: gelu(bank @ fp_w1 + b1) -> g_rin[:, 1024:1280]  [3xtf32]
    mma_gemm<3><<<dim3(PROJ / TBN, NTOK / TBM, 1), 256>>>(
        bank, fp_w1, fp_b1, p_rin + DM,
        PROJ, RAWF, RAWF, RIN, 0, 0, 0, 0,
        nullptr, nullptr, NTOK, 1, 0, out);

    // 3. router layer 1 (fused weights): gelu(g_rin @ g_rw1f + g_rb1f) -> g_rh1 [3xtf32]
    mma_gemm<3><<<dim3(RHID / TBN, NTOK / TBM, 1), 256>>>(
        p_rin, p_rw1f, p_rb1f, p_rh1,
        RHID, RIN, RIN, RHID, 0, 0, 0, 0,
        nullptr, nullptr, NTOK, 1, 0, out);

    // 4. router layer 2 (N=8) -> g_logits  (fp32)
    logits_kernel<<<NTOK / 32, 256>>>(r_w2, r_b2);

    // 5. gate: top-2 softmax + outputs + expert token lists
    gate_kernel<<<NTOK / 256, 256>>>(out);

    // 6. expert GEMM1 (gathered): gelu(h_norm[idx] @ e_w1[z] + b1[z]) -> g_Hbuf[z]
    //    [single tf32]
    mma_gemm<1><<<dim3(EHID / TBN, NTOK / TBM, NE), 256>>>(
        p_hnorm, e_w1, e_b1, p_Hbuf,
        EHID, DM, DM, EHID,
        0, (long)DM * EHID, (long)NTOK * EHID, EHID,
        p_idx, p_cnt, 0, 1, 1, out);

    // 7. expert GEMM2 + weighted scatter into stage_out   [single tf32]
    mma_gemm<1><<<dim3(DM / TBN, NTOK / TBM, NE), 256>>>(
        p_Hbuf, e_w2, e_b2, out,
        DM, EHID, EHID, DM,
        (long)NTOK * EHID, (long)EHID * DM, 0, DM,
        p_idx, p_cnt, 0, 2, 0, out);

    // 8. next_hidden = hidden + alpha * stage_out
    final_kernel<<<NTOK, 256>>>(hidden, alpha, out);
}

// round 16
// speedup vs baseline: 1.4351x; 1.4351x over previous
#include <cuda_runtime.h>
#include <math.h>

#define NTOK 8192
#define DM   1024
#define PROJ 256
#define RHID 256
#define EHID 256
#define NE   8
#define RAWF 512
#define RIN  1280

// output layout (floats), tuple order flattened
#define OFF_NEXT   0L
#define OFF_STAGE  8388608L
#define OFF_GATE   16777216L
#define OFF_SCALED 16842752L
#define OFF_GROUP  16908288L
#define OFF_RULE   16941056L

// scratch (device globals; no allocation allowed)
static __device__ __align__(16) float g_hnorm[NTOK * DM];
static __device__ __align__(16) float g_rin[NTOK * RIN];
static __device__ __align__(16) float g_rh1[NTOK * RHID];
static __device__ __align__(16) float g_logits[NTOK * NE];
static __device__ __align__(16) float g_Hbuf[(long)NE * NTOK * EHID];
static __device__ __align__(16) float g_rw1f[RIN * RHID];   // fused router W1
static __device__ __align__(16) float g_rb1f[RHID];         // fused router b1
static __device__ int g_cnt[NE];
static __device__ int g_idx[NE * NTOK];

__device__ __forceinline__ float gelu_f(float x) {
    const float c = 0.7978845608028654f;
    float t = tanhf(c * (x + 0.044715f * x * x * x));
    return 0.5f * x * (1.0f + t);
}

__device__ __forceinline__ float warpsum(float v) {
    #pragma unroll
    for (int o = 16; o; o >>= 1) v += __shfl_xor_sync(0xFFFFFFFFu, v, o);
    return v;
}

__device__ __forceinline__ float cvt_tf32(float x) {
    unsigned u;
    asm("cvt.rna.tf32.f32 %0, %1;" : "=r"(u) : "f"(x));
    return __uint_as_float(u);
}

__device__ __forceinline__ void mma8(float* c, const unsigned* a, const unsigned* b) {
    asm volatile(
        "mma.sync.aligned.m16n8k8.row.col.f32.tf32.tf32.f32 "
        "{%0,%1,%2,%3}, {%4,%5,%6,%7}, {%8,%9}, {%0,%1,%2,%3};"
        : "+f"(c[0]), "+f"(c[1]), "+f"(c[2]), "+f"(c[3])
        : "r"(a[0]), "r"(a[1]), "r"(a[2]), "r"(a[3]),
          "r"(b[0]), "r"(b[1]));
}

// ---------------------------------------------------------------------------
// Weight fusion: g_rw1f[0:1024] = r_w1[0:1024];
//                g_rw1f[1024+k] = fp_w2[k] @ r_w1[1024:]  (k = 0..255)
//                g_rb1f = r_b1 + fp_b2 @ r_w1[1024:]
// Exact fp32; eliminates the fp-proj layer-2 GEMM entirely.
// ---------------------------------------------------------------------------
__global__ void __launch_bounds__(256) fuse_kernel(
    const float* __restrict__ fp_w2, const float* __restrict__ fp_b2,
    const float* __restrict__ r_w1,  const float* __restrict__ r_b1)
{
    int b = blockIdx.x;
    int n = threadIdx.x;
    if (b < DM) {
        g_rw1f[b * RHID + n] = r_w1[b * RHID + n];
    } else if (b < RIN) {
        int k = b - DM;
        float a0 = 0.f, a1 = 0.f, a2 = 0.f, a3 = 0.f;
        #pragma unroll 4
        for (int j = 0; j < PROJ; j += 4) {
            a0 += fp_w2[k * PROJ + j + 0] * r_w1[(DM + j + 0) * RHID + n];
            a1 += fp_w2[k * PROJ + j + 1] * r_w1[(DM + j + 1) * RHID + n];
            a2 += fp_w2[k * PROJ + j + 2] * r_w1[(DM + j + 2) * RHID + n];
            a3 += fp_w2[k * PROJ + j + 3] * r_w1[(DM + j + 3) * RHID + n];
        }
        g_rw1f[b * RHID + n] = (a0 + a1) + (a2 + a3);
    } else {
        float acc = r_b1[n];
        for (int j = 0; j < PROJ; j++)
            acc += fp_b2[j] * r_w1[(DM + j) * RHID + n];
        g_rb1f[n] = acc;
    }
}

// ---------------------------------------------------------------------------
// Kernel 1: layernorm -> g_hnorm and g_rin[:, :1024]; rule logits; zero
// stage_out region of d_out; zero g_cnt (block 0).
// ---------------------------------------------------------------------------
__global__ void __launch_bounds__(256) ln_kernel(
    const float* __restrict__ hidden,
    const float* __restrict__ ln_g, const float* __restrict__ ln_b,
    const float* __restrict__ feat,
    const float* __restrict__ rr_w, const float* __restrict__ rr_b,
    float* __restrict__ out)
{
    int t = blockIdx.x;
    int tid = threadIdx.x;
    long base = (long)t * DM + tid * 4;
    float4 x = *(const float4*)(hidden + base);

    float s1 = x.x + x.y + x.z + x.w;
    float s2 = x.x * x.x + x.y * x.y + x.z * x.z + x.w * x.w;

    __shared__ float sm1[8], sm2[8];
    float w1 = warpsum(s1), w2 = warpsum(s2);
    if ((tid & 31) == 0) { sm1[tid >> 5] = w1; sm2[tid >> 5] = w2; }
    __syncthreads();
    __shared__ float s_mu, s_inv;
    if (tid == 0) {
        float a = 0.f, c = 0.f;
        #pragma unroll
        for (int i = 0; i < 8; i++) { a += sm1[i]; c += sm2[i]; }
        float m = a * (1.0f / DM);
        float var = c * (1.0f / DM) - m * m;
        s_mu = m;
        s_inv = rsqrtf(var + 1e-5f);
    }
    __syncthreads();
    float mu = s_mu, inv = s_inv;

    float4 gg = *(const float4*)(ln_g + tid * 4);
    float4 bb = *(const float4*)(ln_b + tid * 4);
    float4 y;
    y.x = (x.x - mu) * inv * gg.x + bb.x;
    y.y = (x.y - mu) * inv * gg.y + bb.y;
    y.z = (x.z - mu) * inv * gg.z + bb.z;
    y.w = (x.w - mu) * inv * gg.w + bb.w;

    *(float4*)(g_hnorm + base) = y;
    *(float4*)(g_rin + (long)t * RIN + tid * 4) = y;

    float4 z4 = make_float4(0.f, 0.f, 0.f, 0.f);
    *(float4*)(out + OFF_STAGE + base) = z4;

    if (tid < NE) {
        float acc = rr_b[tid];
        #pragma unroll
        for (int k = 0; k < 16; k++) acc += feat[t * 16 + k] * rr_w[k * NE + tid];
        out[OFF_RULE + (long)t * NE + tid] = acc;
    }
    if (t == 0 && tid < NE) g_cnt[tid] = 0;
}

// ---------------------------------------------------------------------------
// tf32 tensor-core GEMM, templated precision / tile height / occupancy:
//   PREC=3: 3xtf32 split (fp32-grade, routing-critical GEMMs)
//   PREC=1: single-pass tf32 (~2e-4, expert GEMMs after gating)
//   MT: m-tiles (16 rows each) per warp. MT=4 -> TBM=128 (R11-identical
//       codegen). MT=2 -> TBM=64, acc halves to 32 floats/thread, so
//       MINB=2 (2 CTAs/SM, 128-reg cap) fits WITHOUT spilling — this is
//       the R8 spill lesson applied: cap only when acc is small enough.
// Double-buffered SMEM, one __syncthreads per K-slab.
// 256 threads = 8 warps (2x4), warp tile (MT*16)x32.
// mode: 0 = store, 1 = gelu+store, 2 = weighted atomic scatter to stage_out.
// gatherA: A rows indirected through idx (expert GEMM1).
// ---------------------------------------------------------------------------
#define TBN 128
#define TBK 16
#define APAD 20
#define BPAD 136

template<int PREC, int MT, int MINB>
__global__ void __launch_bounds__(256, MINB) mma_gemm(
    const float* __restrict__ A,
    const float* __restrict__ Bw,
    const float* __restrict__ bias,
    float* __restrict__ C,
    int N, int K, int lda, int ldc,
    long aStride, long bStride, long cStride, int biasStride,
    const int* __restrict__ gIdx,
    const int* __restrict__ cntArr,
    int Mfixed, int mode, int gatherA,
    float* __restrict__ outbase)
{
    const int TBM = 32 * MT;
    const int NJA = MT / 2;          // A-staging float4s per thread

    int z = blockIdx.z;
    int M = cntArr ? cntArr[z] : Mfixed;
    int m0 = blockIdx.y * TBM;
    if (m0 >= M) return;
    int n0 = blockIdx.x * TBN;
    const float* Az = A + (long)z * aStride;
    const float* B = Bw + (long)z * bStride;
    float* Cz = C + (long)z * cStride;
    const float* bz = bias + (long)z * biasStride;
    const int* idx = gIdx ? (gIdx + z * NTOK) : (const int*)0;

    __shared__ float As_hi[2][32 * MT][APAD];
    __shared__ float Bs_hi[2][TBK][BPAD];
    __shared__ float As_lo[PREC == 3 ? 2 : 1][32 * MT][APAD];
    __shared__ float Bs_lo[PREC == 3 ? 2 : 1][TBK][BPAD];

    int tid = threadIdx.x;

    // A staging: NJA float4/thread; id -> m-row = id>>2, k-quad = id&3
    long aOff[NJA]; bool aV[NJA];
    #pragma unroll
    for (int j = 0; j < NJA; j++) {
        int id = tid + 256 * j;
        int r = id >> 2, c4 = id & 3;
        int gm = m0 + r;
        aV[j] = gm < M;
        int gr = 0;
        if (aV[j]) gr = gatherA ? idx[gm] : gm;
        aOff[j] = (long)gr * lda + c4 * 4;
    }

    float4 ra[NJA], rb[2];
    #pragma unroll
    for (int j = 0; j < NJA; j++)
        ra[j] = aV[j] ? *(const float4*)(Az + aOff[j]) : make_float4(0.f,0.f,0.f,0.f);
    #pragma unroll
    for (int j = 0; j < 2; j++) {
        int id = tid + 256 * j;
        int r = id >> 5, c4 = id & 31;
        rb[j] = *(const float4*)(B + (long)r * N + n0 + c4 * 4);
    }

    float acc[MT][4][4];
    #pragma unroll
    for (int a = 0; a < MT; a++)
        #pragma unroll
        for (int b = 0; b < 4; b++)
            #pragma unroll
            for (int cc = 0; cc < 4; cc++) acc[a][b][cc] = 0.f;

    int wid = tid >> 5, lane = tid & 31;
    int wm = (wid >> 2) * (MT * 16), wn = (wid & 3) * 32;
    int g = lane >> 2, q = lane & 3;

    int buf = 0;
    for (int k0 = 0; k0 < K; k0 += TBK) {
        // commit staged regs to smem[buf]
        #pragma unroll
        for (int j = 0; j < NJA; j++) {
            int id = tid + 256 * j;
            int r = id >> 2, c = (id & 3) * 4;
            float v[4] = { ra[j].x, ra[j].y, ra[j].z, ra[j].w };
            #pragma unroll
            for (int i = 0; i < 4; i++) {
                float h = cvt_tf32(v[i]);
                As_hi[buf][r][c + i] = h;
                if (PREC == 3) As_lo[buf][r][c + i] = cvt_tf32(v[i] - h);
            }
        }
        #pragma unroll
        for (int j = 0; j < 2; j++) {
            int id = tid + 256 * j;
            int r = id >> 5, c = (id & 31) * 4;
            float v[4] = { rb[j].x, rb[j].y, rb[j].z, rb[j].w };
            #pragma unroll
            for (int i = 0; i < 4; i++) {
                float h = cvt_tf32(v[i]);
                Bs_hi[buf][r][c + i] = h;
                if (PREC == 3) Bs_lo[buf][r][c + i] = cvt_tf32(v[i] - h);
            }
        }
        __syncthreads();

        // prefetch next K-slab into regs (overlaps with compute below)
        if (k0 + TBK < K) {
            #pragma unroll
            for (int j = 0; j < NJA; j++)
                ra[j] = aV[j] ? *(const float4*)(Az + aOff[j] + k0 + TBK)
                              : make_float4(0.f,0.f,0.f,0.f);
            #pragma unroll
            for (int j = 0; j < 2; j++) {
                int id = tid + 256 * j;
                int r = id >> 5, c4 = id & 31;
                rb[j] = *(const float4*)(B + (long)(k0 + TBK + r) * N + n0 + c4 * 4);
            }
        }

        #pragma unroll
        for (int ks = 0; ks < 2; ks++) {
            int kk = ks * 8;
            unsigned ah[MT][4], al[MT][4], bh[4][2], bl[4][2];
            #pragma unroll
            for (int mt = 0; mt < MT; mt++) {
                int mr = wm + mt * 16 + g;
                ah[mt][0] = __float_as_uint(As_hi[buf][mr][kk + q]);
                ah[mt][1] = __float_as_uint(As_hi[buf][mr + 8][kk + q]);
                ah[mt][2] = __float_as_uint(As_hi[buf][mr][kk + q + 4]);
                ah[mt][3] = __float_as_uint(As_hi[buf][mr + 8][kk + q + 4]);
                if (PREC == 3) {
                    al[mt][0] = __float_as_uint(As_lo[buf][mr][kk + q]);
                    al[mt][1] = __float_as_uint(As_lo[buf][mr + 8][kk + q]);
                    al[mt][2] = __float_as_uint(As_lo[buf][mr][kk + q + 4]);
                    al[mt][3] = __float_as_uint(As_lo[buf][mr + 8][kk + q + 4]);
                }
            }
            #pragma unroll
            for (int nt = 0; nt < 4; nt++) {
                int nc = wn + nt * 8 + g;
                bh[nt][0] = __float_as_uint(Bs_hi[buf][kk + q][nc]);
                bh[nt][1] = __float_as_uint(Bs_hi[buf][kk + q + 4][nc]);
                if (PREC == 3) {
                    bl[nt][0] = __float_as_uint(Bs_lo[buf][kk + q][nc]);
                    bl[nt][1] = __float_as_uint(Bs_lo[buf][kk + q + 4][nc]);
                }
            }
            #pragma unroll
            for (int mt = 0; mt < MT; mt++)
                #pragma unroll
                for (int nt = 0; nt < 4; nt++) {
                    if (PREC == 3) {
                        mma8(acc[mt][nt], al[mt], bh[nt]);
                        mma8(acc[mt][nt], ah[mt], bl[nt]);
                    }
                    mma8(acc[mt][nt], ah[mt], bh[nt]);
                }
        }
        buf ^= 1;
    }

    // epilogue
    #pragma unroll
    for (int mt = 0; mt < MT; mt++) {
        int r0 = m0 + wm + mt * 16 + g;
        int r1 = r0 + 8;
        #pragma unroll
        for (int nt = 0; nt < 4; nt++) {
            int col = n0 + wn + nt * 8 + 2 * q;
            float b0 = bz[col], b1 = bz[col + 1];
            float v00 = acc[mt][nt][0] + b0, v01 = acc[mt][nt][1] + b1;
            float v10 = acc[mt][nt][2] + b0, v11 = acc[mt][nt][3] + b1;
            if (mode == 1) {
                v00 = gelu_f(v00); v01 = gelu_f(v01);
                v10 = gelu_f(v10); v11 = gelu_f(v11);
            }
            if (mode <= 1) {
                if (r0 < M) { float2 v = make_float2(v00, v01);
                              *(float2*)(Cz + (long)r0 * ldc + col) = v; }
                if (r1 < M) { float2 v = make_float2(v10, v11);
                              *(float2*)(Cz + (long)r1 * ldc + col) = v; }
            } else {
                if (r0 < M) {
                    int tok = idx[r0];
                    float w = outbase[OFF_GATE + (long)tok * NE + z];
                    float* dst = outbase + OFF_STAGE + (long)tok * DM + col;
                    atomicAdd(dst + 0, w * v00);
                    atomicAdd(dst + 1, w * v01);
                }
                if (r1 < M) {
                    int tok = idx[r1];
                    float w = outbase[OFF_GATE + (long)tok * NE + z];
                    float* dst = outbase + OFF_STAGE + (long)tok * DM + col;
                    atomicAdd(dst + 0, w * v10);
                    atomicAdd(dst + 1, w * v11);
                }
            }
        }
    }
}

// ---------------------------------------------------------------------------
// Router logits: g_logits = g_rh1 @ r_w2 + r_b2   (N=8, fp32)
// ---------------------------------------------------------------------------
__global__ void __launch_bounds__(256) logits_kernel(
    const float* __restrict__ r_w2, const float* __restrict__ r_b2)
{
    __shared__ float sh[32 * 257];
    __shared__ float w2s[RHID * NE];
    int tid = threadIdx.x;
    int t0 = blockIdx.x * 32;
    for (int i = tid; i < 32 * RHID; i += 256) {
        int r = i >> 8, c = i & 255;
        sh[r * 257 + c] = g_rh1[(long)(t0 + r) * RHID + c];
    }
    for (int i = tid; i < RHID * NE; i += 256) w2s[i] = r_w2[i];
    __syncthreads();
    int j = tid >> 3, e = tid & 7;
    float acc = r_b2[e];
    #pragma unroll 8
    for (int k = 0; k < RHID; k++) acc += sh[j * 257 + k] * w2s[k * NE + e];
    g_logits[(long)(t0 + j) * NE + e] = acc;
}

// ---------------------------------------------------------------------------
// Gate: exact top-2-with-ties softmax, write gate/scaled/group outputs,
// build per-expert token lists.
// ---------------------------------------------------------------------------
__global__ void __launch_bounds__(256) gate_kernel(float* __restrict__ out)
{
    int t = blockIdx.x * blockDim.x + threadIdx.x;
    if (t >= NTOK) return;
    float l[8];
    #pragma unroll
    for (int e = 0; e < NE; e++) l[e] = g_logits[(long)t * NE + e];

    float m1 = -INFINITY, m2 = -INFINITY;
    #pragma unroll
    for (int e = 0; e < NE; e++) {
        float v = l[e];
        if (v > m1) { m2 = m1; m1 = v; }
        else if (v > m2) { m2 = v; }
    }
    float thresh = m2;

    float w[8];
    float sum = 0.f;
    #pragma unroll
    for (int e = 0; e < NE; e++) {
        if (l[e] >= thresh) { w[e] = expf(l[e] - m1); sum += w[e]; }
        else w[e] = 0.f;
    }
    float rinv = 1.0f / sum;
    #pragma unroll
    for (int e = 0; e < NE; e++) {
        float ww = w[e] * rinv;
        out[OFF_GATE + (long)t * NE + e] = ww;
        out[OFF_SCALED + (long)t * NE + e] = l[e];
        if (l[e] >= thresh) {
            int s = atomicAdd(&g_cnt[e], 1);
            g_idx[e * NTOK + s] = t;
        }
        w[e] = ww;
    }
    #pragma unroll
    for (int g = 0; g < NE / 2; g++)
        out[OFF_GROUP + (long)t * (NE / 2) + g] = w[2 * g] + w[2 * g + 1];
}

// ---------------------------------------------------------------------------
// Final: next_hidden = hidden + alpha * stage_out
// ---------------------------------------------------------------------------
__global__ void __launch_bounds__(256) final_kernel(
    const float* __restrict__ hidden,
    const float* __restrict__ alpha,
    float* __restrict__ out)
{
    long i = ((long)blockIdx.x * 256 + threadIdx.x) * 4;
    float a = *alpha;
    float4 h = *(const float4*)(hidden + i);
    float4 s = *(const float4*)(out + OFF_STAGE + i);
    float4 n;
    n.x = h.x + a * s.x; n.y = h.y + a * s.y;
    n.z = h.z + a * s.z; n.w = h.w + a * s.w;
    *(float4*)(out + OFF_NEXT + i) = n;
}

// ---------------------------------------------------------------------------
extern "C" void kernel_launch(void* const* d_in, const int* in_sizes, int n_in,
                              void* d_out, int out_size)
{
    const float* hidden = (const float*)d_in[0];
    const float* feat   = (const float*)d_in[1];
    const float* bank   = (const float*)d_in[2];   // (tok, 512)
    const float* ln_g  = (const float*)d_in[4];
    const float* ln_b  = (const float*)d_in[5];
    const float* fp_w1 = (const float*)d_in[6];
    const float* fp_b1 = (const float*)d_in[7];
    const float* fp_w2 = (const float*)d_in[8];
    const float* fp_b2 = (const float*)d_in[9];
    const float* r_w1  = (const float*)d_in[10];
    const float* r_b1  = (const float*)d_in[11];
    const float* r_w2  = (const float*)d_in[12];
    const float* r_b2  = (const float*)d_in[13];
    const float* rr_w  = (const float*)d_in[14];
    const float* rr_b  = (const float*)d_in[15];
    const float* e_w1  = (const float*)d_in[16];
    const float* e_b1  = (const float*)d_in[17];
    const float* e_w2  = (const float*)d_in[18];
    const float* e_b2  = (const float*)d_in[19];
    const float* alpha = (const float*)d_in[20];
    float* out = (float*)d_out;

    float *p_hnorm, *p_rin, *p_rh1, *p_Hbuf, *p_rw1f, *p_rb1f;
    int *p_cnt, *p_idx;
    cudaGetSymbolAddress((void**)&p_hnorm, g_hnorm);
    cudaGetSymbolAddress((void**)&p_rin,   g_rin);
    cudaGetSymbolAddress((void**)&p_rh1,   g_rh1);
    cudaGetSymbolAddress((void**)&p_Hbuf,  g_Hbuf);
    cudaGetSymbolAddress((void**)&p_rw1f,  g_rw1f);
    cudaGetSymbolAddress((void**)&p_rb1f,  g_rb1f);
    cudaGetSymbolAddress((void**)&p_cnt,   g_cnt);
    cudaGetSymbolAddress((void**)&p_idx,   g_idx);

    // 0. fuse fp_w2 into router W1 (exact fp32; removes fp-proj GEMM 2)
    fuse_kernel<<<RIN + 1, 256>>>(fp_w2, fp_b2, r_w1, r_b1);

    // 1. layernorm (+ rule logits, zero stage_out & counters)
    ln_kernel<<<NTOK, 256>>>(hidden, ln_g, ln_b, feat, rr_w, rr_b, out);

    // 2. feat proj layer 1: gelu(bank @ fp_w1 + b1) -> g_rin[:, 1024:1280]
    //    [3xtf32, TBM=128 — R11-identical codegen]
    mma_gemm<3, 4, 1><<<dim3(PROJ / TBN, NTOK / 128, 1), 256>>>(
        bank, fp_w1, fp_b1, p_rin + DM,
        PROJ, RAWF, RAWF, RIN, 0, 0, 0, 0,
        nullptr, nullptr, NTOK, 1, 0, out);

    // 3. router layer 1 (fused weights): gelu(g_rin @ g_rw1f + g_rb1f) -> g_rh1
    //    [3xtf32, TBM=128]
    mma_gemm<3, 4, 1><<<dim3(RHID / TBN, NTOK / 128, 1), 256>>>(
        p_rin, p_rw1f, p_rb1f, p_rh1,
        RHID, RIN, RIN, RHID, 0, 0, 0, 0,
        nullptr, nullptr, NTOK, 1, 0, out);

    // 4. router layer 2 (N=8) -> g_logits  (fp32)
    logits_kernel<<<NTOK / 32, 256>>>(r_w2, r_b2);

    // 5. gate: top-2 softmax + outputs + expert token lists
    gate_kernel<<<NTOK / 256, 256>>>(out);

    // 6. expert GEMM1 (gathered): gelu(h_norm[idx] @ e_w1[z] + b1[z]) -> g_Hbuf[z]
    //    [single tf32, TBM=64, 2 CTAs/SM]
    mma_gemm<1, 2, 2><<<dim3(EHID / TBN, NTOK / 64, NE), 256>>>(
        p_hnorm, e_w1, e_b1, p_Hbuf,
        EHID, DM, DM, EHID,
        0, (long)DM * EHID, (long)NTOK * EHID, EHID,
        p_idx, p_cnt, 0, 1, 1, out);

    // 7. expert GEMM2 + weighted scatter into stage_out
    //    [single tf32, TBM=64, 2 CTAs/SM]
    mma_gemm<1, 2, 2><<<dim3(DM / TBN, NTOK / 64, NE), 256>>>(
        p_Hbuf, e_w2, e_b2, out,
        DM, EHID, EHID, DM,
        (long)NTOK * EHID, (long)EHID * DM, 0, DM,
        p_idx, p_cnt, 0, 2, 0, out);

    // 8. next_hidden = hidden + alpha * stage_out
    final_kernel<<<NTOK, 256>>>(hidden, alpha, out);
}